// round 1
// baseline (speedup 1.0000x reference)
#include <cuda_runtime.h>
#include <math.h>

// ---------------- problem constants ----------------
#define B_    4
#define LRAW  8000
#define D_    512
#define NLAY  4
#define NS    16
#define DI    1024
#define RK    32
#define L1C   1600
#define LL    800
#define C4    128
#define ROWS  (B_*LL)          // 3200

// ---------------- scratch (device globals; no allocation) ----------------
__device__ float g_h  [ROWS*D_];
__device__ float g_u  [ROWS*D_];
__device__ float g_xz [ROWS*2*DI];
__device__ float g_xc [ROWS*DI];
__device__ float g_dbl[ROWS*64];
__device__ float g_dt [ROWS*DI];
__device__ float g_y  [ROWS*DI];
__device__ float g_s1 [B_*C4*L1C];
__device__ float g_col[ROWS*C4*3];
__device__ float g_bnp[2*D_];
__device__ float g_part[32*D_];

// ---------------- conv stem ----------------
__global__ void conv1_k(const float* __restrict__ x, const float* __restrict__ w,
                        const float* __restrict__ bias,
                        const float* __restrict__ bg, const float* __restrict__ bb,
                        const float* __restrict__ bm, const float* __restrict__ bv)
{
    int idx = blockIdx.x*256 + threadIdx.x;          // (b*C4+c)*L1C + l
    if (idx >= B_*C4*L1C) return;
    int l = idx % L1C;
    int c = (idx / L1C) % C4;
    int b = idx / (L1C*C4);
    float acc = bias[c];
    const float* xb = x + (size_t)b*LRAW;
    int p0 = l*5 - 3;
#pragma unroll
    for (int k = 0; k < 10; k++) {
        int p = p0 + k;
        if (p >= 0 && p < LRAW) acc += xb[p] * w[c*10 + k];
    }
    float s = bg[c] * rsqrtf(bv[c] + 1e-5f);
    float t = (acc - bm[c]) * s + bb[c];
    g_s1[idx] = t / (1.f + __expf(-t));              // SiLU
}

__global__ void bnprep_k(const float* __restrict__ cb,
                         const float* __restrict__ bg, const float* __restrict__ bb,
                         const float* __restrict__ bm, const float* __restrict__ bv)
{
    int c = threadIdx.x;                              // 512 threads
    float s = bg[c] * rsqrtf(bv[c] + 1e-5f);
    g_bnp[c]      = s;
    g_bnp[D_ + c] = (cb[c] - bm[c]) * s + bb[c];
}

__global__ void im2col_k()
{
    int idx = blockIdx.x*256 + threadIdx.x;           // ROWS*384
    if (idx >= ROWS*C4*3) return;
    int j = idx % (C4*3);
    int m = idx / (C4*3);
    int b = m / LL, l = m % LL;
    int ci = j / 3, kk = j % 3;
    int p = 2*l - 1 + kk;
    g_col[idx] = (p >= 0 && p < L1C) ? g_s1[(b*C4 + ci)*L1C + p] : 0.f;
}

// ---------------- LayerNorm over D=512, one warp per row ----------------
__global__ void ln_k(const float* __restrict__ x, const float* __restrict__ g,
                     const float* __restrict__ bt, float* __restrict__ o)
{
    int row  = (blockIdx.x*blockDim.x + threadIdx.x) >> 5;   // 3200 rows
    int lane = threadIdx.x & 31;
    const float* xp = x + (size_t)row*D_;
    float v[16];
    float s = 0.f;
#pragma unroll
    for (int i = 0; i < 16; i++) { v[i] = xp[lane + 32*i]; s += v[i]; }
#pragma unroll
    for (int m = 16; m; m >>= 1) s += __shfl_xor_sync(0xffffffffu, s, m);
    float mu = s * (1.f/512.f);
    float vs = 0.f;
#pragma unroll
    for (int i = 0; i < 16; i++) { float d = v[i]-mu; vs += d*d; }
#pragma unroll
    for (int m = 16; m; m >>= 1) vs += __shfl_xor_sync(0xffffffffu, vs, m);
    float inv = rsqrtf(vs * (1.f/512.f) + 1e-5f);
    float* op = o + (size_t)row*D_;
#pragma unroll
    for (int i = 0; i < 16; i++) {
        int c = lane + 32*i;
        op[c] = (v[i]-mu)*inv*g[c] + bt[c];
    }
}

// ---------------- generic NT SGEMM: C[M,N] = A[M,K(lda)] * B[N,K(ldb)]^T ----------------
// modes: 0 store, 1 scale/shift (e1[col],e1[N+col]), 2 bias+softplus, 3 bias+gelu,
//        4 residual (+=), 5 bias+residual
template<int BM, int BN, int TM, int TN>
__global__ void __launch_bounds__(256)
gemm_nt(int M, int N, int K, int lda, int ldb,
        const float* __restrict__ A, const float* __restrict__ B,
        float* __restrict__ C, int mode, const float* __restrict__ e1)
{
    constexpr int BK = 16;
    __shared__ float As[BK][BM+4];
    __shared__ float Bs[BK][BN+4];
    const int tid = threadIdx.x;
    const int bn = blockIdx.x, bm = blockIdx.y;
    const int tx = tid % (BN/TN), ty = tid / (BN/TN);
    float acc[TM][TN];
#pragma unroll
    for (int i = 0; i < TM; i++)
#pragma unroll
        for (int j = 0; j < TN; j++) acc[i][j] = 0.f;

    const float* Ab = A + (size_t)bm*BM*lda;
    const float* Bb = B + (size_t)bn*BN*ldb;

    for (int k0 = 0; k0 < K; k0 += BK) {
#pragma unroll
        for (int v = tid; v < BM*4; v += 256) {
            int r = v >> 2, c = (v & 3) * 4;
            float4 f = *(const float4*)(Ab + (size_t)r*lda + k0 + c);
            As[c+0][r] = f.x; As[c+1][r] = f.y; As[c+2][r] = f.z; As[c+3][r] = f.w;
        }
#pragma unroll
        for (int v = tid; v < BN*4; v += 256) {
            int r = v >> 2, c = (v & 3) * 4;
            float4 f = *(const float4*)(Bb + (size_t)r*ldb + k0 + c);
            Bs[c+0][r] = f.x; Bs[c+1][r] = f.y; Bs[c+2][r] = f.z; Bs[c+3][r] = f.w;
        }
        __syncthreads();
#pragma unroll
        for (int kk = 0; kk < BK; kk++) {
            float ra[TM], rb[TN];
#pragma unroll
            for (int i = 0; i < TM; i += 4) {
                float4 f = *(const float4*)&As[kk][ty*TM + i];
                ra[i] = f.x; ra[i+1] = f.y; ra[i+2] = f.z; ra[i+3] = f.w;
            }
#pragma unroll
            for (int j = 0; j < TN; j += 4) {
                float4 f = *(const float4*)&Bs[kk][tx*TN + j];
                rb[j] = f.x; rb[j+1] = f.y; rb[j+2] = f.z; rb[j+3] = f.w;
            }
#pragma unroll
            for (int i = 0; i < TM; i++)
#pragma unroll
                for (int j = 0; j < TN; j++)
                    acc[i][j] = fmaf(ra[i], rb[j], acc[i][j]);
        }
        __syncthreads();
    }

#pragma unroll
    for (int i = 0; i < TM; i++) {
        int row = bm*BM + ty*TM + i;
        float* Cr = C + (size_t)row*N + bn*BN + tx*TN;
#pragma unroll
        for (int j = 0; j < TN; j++) {
            int col = bn*BN + tx*TN + j;
            float v = acc[i][j];
            if (mode == 1) {
                v = v*e1[col] + e1[N + col];
            } else if (mode == 2) {
                float t = v + e1[col];
                v = fmaxf(t, 0.f) + log1pf(__expf(-fabsf(t)));
            } else if (mode == 3) {
                float t = v + e1[col];
                v = 0.5f*t*(1.f + erff(t*0.70710678118f));
            } else if (mode == 4) {
                v += Cr[j];
            } else if (mode == 5) {
                v += Cr[j] + e1[col];
            }
            Cr[j] = v;
        }
    }
}

// ---------------- causal depthwise conv (k=4) + SiLU ----------------
__global__ void dwconv_k(const float* __restrict__ cw, const float* __restrict__ cb)
{
    int idx = blockIdx.x*256 + threadIdx.x;          // ROWS*DI
    if (idx >= ROWS*DI) return;
    int d = idx & (DI-1);
    int row = idx >> 10;
    int l = row % LL;
    float s = cb[d];
    const float* base = g_xz + (size_t)(row-3)*2*DI + d;   // xm = first DI cols
#pragma unroll
    for (int k = 0; k < 4; k++) {
        int lk = l - 3 + k;
        if (lk >= 0) s += base[k*2*DI] * cw[d*4 + k];
    }
    g_xc[idx] = s / (1.f + __expf(-s));
}

// ---------------- selective scan: 1 state per thread, 16 lanes per (b,d) channel ----
__global__ void scan_k(const float* __restrict__ A_log, const float* __restrict__ Dp)
{
    int gid  = blockIdx.x*128 + threadIdx.x;   // 65536 threads
    int ch   = gid >> 4;                       // b*DI + d
    int n    = gid & 15;
    int b    = ch >> 10;
    int d    = ch & (DI-1);

    float A   = -__expf(A_log[d*NS + n]);
    float Dpv = Dp[d];
    float h   = 0.f;

    const float* dtp = g_dt  + (size_t)(b*LL)*DI + d;
    const float* xcp = g_xc  + (size_t)(b*LL)*DI + d;
    const float* zp  = g_xz  + (size_t)(b*LL)*2*DI + DI + d;
    const float* bcp = g_dbl + (size_t)(b*LL)*64 + 32 + n;   // B at +0, C at +16
    float*       yp  = g_y   + (size_t)(b*LL)*DI + d;

    for (int t = 0; t < LL; t++) {
        float dtv = dtp[(size_t)t*DI];
        float xv  = xcp[(size_t)t*DI];
        float Bn  = bcp[(size_t)t*64];
        float Cn  = bcp[(size_t)t*64 + 16];
        float w   = __expf(dtv * A);
        h = h*w + dtv*xv*Bn;
        float part = h * Cn;
        part += __shfl_xor_sync(0xffffffffu, part, 8);
        part += __shfl_xor_sync(0xffffffffu, part, 4);
        part += __shfl_xor_sync(0xffffffffu, part, 2);
        part += __shfl_xor_sync(0xffffffffu, part, 1);
        if (n == 0) {
            float zv  = zp[(size_t)t*2*DI];
            float sil = zv / (1.f + __expf(-zv));
            yp[(size_t)t*DI] = (part + xv*Dpv) * sil;
        }
    }
}

// ---------------- mean over L (two-stage, deterministic) ----------------
__global__ void mean_part_k()
{
    int d = threadIdx.x;                 // 512
    int b = blockIdx.x & 3;
    int chunk = blockIdx.x >> 2;         // 8 chunks of 100
    float s = 0.f;
    const float* up = g_u + (size_t)(b*LL + chunk*100)*D_ + d;
    for (int l = 0; l < 100; l++) s += up[(size_t)l*D_];
    g_part[blockIdx.x*D_ + d] = s;
}
__global__ void mean_fin_k(float* __restrict__ out)
{
    int i = blockIdx.x*256 + threadIdx.x;   // 2048
    int b = i >> 9, d = i & 511;
    float s = 0.f;
#pragma unroll
    for (int c = 0; c < 8; c++) s += g_part[(c*4 + b)*D_ + d];
    out[i] = s * (1.f/800.f);
}

// ---------------- driver ----------------
extern "C" void kernel_launch(void* const* d_in, const int* in_sizes, int n_in,
                              void* d_out, int out_size)
{
    const float* x    = (const float*)d_in[0];
    const float* c1w  = (const float*)d_in[1];
    const float* c1b  = (const float*)d_in[2];
    const float* b1g  = (const float*)d_in[3];
    const float* b1b  = (const float*)d_in[4];
    const float* b1m  = (const float*)d_in[5];
    const float* b1v  = (const float*)d_in[6];
    const float* c2w  = (const float*)d_in[7];
    const float* c2b  = (const float*)d_in[8];
    const float* b2g  = (const float*)d_in[9];
    const float* b2b  = (const float*)d_in[10];
    const float* b2m  = (const float*)d_in[11];
    const float* b2v  = (const float*)d_in[12];
    const float* ln1g = (const float*)d_in[13];
    const float* ln1b = (const float*)d_in[14];
    const float* inw  = (const float*)d_in[15];
    const float* cw   = (const float*)d_in[16];
    const float* cb   = (const float*)d_in[17];
    const float* xpw  = (const float*)d_in[18];
    const float* dtw  = (const float*)d_in[19];
    const float* dtb  = (const float*)d_in[20];
    const float* alog = (const float*)d_in[21];
    const float* dp   = (const float*)d_in[22];
    const float* outw = (const float*)d_in[23];
    const float* ln2g = (const float*)d_in[24];
    const float* ln2b = (const float*)d_in[25];
    const float* m1w  = (const float*)d_in[26];
    const float* m1b  = (const float*)d_in[27];
    const float* m2w  = (const float*)d_in[28];
    const float* m2b  = (const float*)d_in[29];
    const float* fng  = (const float*)d_in[30];
    const float* fnb  = (const float*)d_in[31];

    float *h, *u, *xz, *xc, *dbl, *dt, *y, *col, *bnp;
    cudaGetSymbolAddress((void**)&h,   g_h);
    cudaGetSymbolAddress((void**)&u,   g_u);
    cudaGetSymbolAddress((void**)&xz,  g_xz);
    cudaGetSymbolAddress((void**)&xc,  g_xc);
    cudaGetSymbolAddress((void**)&dbl, g_dbl);
    cudaGetSymbolAddress((void**)&dt,  g_dt);
    cudaGetSymbolAddress((void**)&y,   g_y);
    cudaGetSymbolAddress((void**)&col, g_col);
    cudaGetSymbolAddress((void**)&bnp, g_bnp);

    // ---- stem ----
    conv1_k<<<(B_*C4*L1C + 255)/256, 256>>>(x, c1w, c1b, b1g, b1b, b1m, b1v);
    bnprep_k<<<1, 512>>>(c2b, b2g, b2b, b2m, b2v);
    im2col_k<<<(ROWS*C4*3 + 255)/256, 256>>>();
    gemm_nt<128,128,8,8><<<dim3(D_/128, ROWS/128), 256>>>(
        ROWS, D_, C4*3, C4*3, C4*3, col, c2w, h, 1, bnp);

    // ---- layers ----
    for (int i = 0; i < NLAY; i++) {
        ln_k<<<ROWS/8, 256>>>(h, ln1g + i*D_, ln1b + i*D_, u);
        gemm_nt<128,128,8,8><<<dim3(2*DI/128, ROWS/128), 256>>>(
            ROWS, 2*DI, D_, D_, D_, u, inw + (size_t)i*2*DI*D_, xz, 0, nullptr);
        dwconv_k<<<(ROWS*DI + 255)/256, 256>>>(cw + (size_t)i*DI*4, cb + i*DI);
        gemm_nt<64,64,4,4><<<dim3(1, ROWS/64), 256>>>(
            ROWS, 64, DI, DI, DI, xc, xpw + (size_t)i*64*DI, dbl, 0, nullptr);
        gemm_nt<128,128,8,8><<<dim3(DI/128, ROWS/128), 256>>>(
            ROWS, DI, RK, 64, RK, dbl, dtw + (size_t)i*DI*RK, dt, 2, dtb + i*DI);
        scan_k<<<512, 128>>>(alog + (size_t)i*DI*NS, dp + i*DI);
        gemm_nt<128,128,8,8><<<dim3(D_/128, ROWS/128), 256>>>(
            ROWS, D_, DI, DI, DI, y, outw + (size_t)i*D_*DI, h, 4, nullptr);

        ln_k<<<ROWS/8, 256>>>(h, ln2g + i*D_, ln2b + i*D_, u);
        gemm_nt<128,128,8,8><<<dim3(DI/128, ROWS/128), 256>>>(
            ROWS, DI, D_, D_, D_, u, m1w + (size_t)i*DI*D_, xc, 3, m1b + i*DI);
        gemm_nt<128,128,8,8><<<dim3(D_/128, ROWS/128), 256>>>(
            ROWS, D_, DI, DI, DI, xc, m2w + (size_t)i*D_*DI, h, 5, m2b + i*D_);
    }

    // ---- final LN + mean ----
    ln_k<<<ROWS/8, 256>>>(h, fng, fnb, u);
    mean_part_k<<<32, 512>>>();
    mean_fin_k<<<8, 256>>>((float*)d_out);
}

// round 2
// speedup vs baseline: 1.5208x; 1.5208x over previous
#include <cuda_runtime.h>
#include <math.h>
#include <stdint.h>

// ---------------- problem constants ----------------
#define B_    4
#define LRAW  8000
#define D_    512
#define NLAY  4
#define NS    16
#define DI    1024
#define RK    32
#define L1C   1600
#define LL    800
#define C4    128
#define ROWS  (B_*LL)          // 3200

// ---------------- scratch (device globals; no allocation) ----------------
__device__ float g_h  [ROWS*D_];
__device__ float g_u  [ROWS*D_];
__device__ float g_xz [ROWS*2*DI];
__device__ float g_xc [ROWS*DI];
__device__ float g_dbl[ROWS*64];
__device__ float g_dt [ROWS*DI];
__device__ float g_y  [ROWS*DI];
__device__ float g_s1 [B_*C4*L1C];
__device__ float g_col[ROWS*C4*3];
__device__ float g_bnp[2*D_];
__device__ float g_part[32*D_];

// ---------------- PTX helpers ----------------
__device__ __forceinline__ void cpa16(uint32_t s, const void* g) {
    asm volatile("cp.async.ca.shared.global [%0], [%1], 16;" :: "r"(s), "l"(g));
}
__device__ __forceinline__ void ldsm4(uint32_t& r0, uint32_t& r1, uint32_t& r2, uint32_t& r3,
                                      uint32_t addr) {
    asm volatile("ldmatrix.sync.aligned.m8n8.x4.shared.b16 {%0,%1,%2,%3}, [%4];"
        : "=r"(r0), "=r"(r1), "=r"(r2), "=r"(r3) : "r"(addr));
}
__device__ __forceinline__ void mma_tf32(float* c, const uint32_t* a, const uint32_t* b) {
    asm volatile("mma.sync.aligned.m16n8k8.row.col.f32.tf32.tf32.f32 "
        "{%0,%1,%2,%3},{%4,%5,%6,%7},{%8,%9},{%0,%1,%2,%3};"
        : "+f"(c[0]), "+f"(c[1]), "+f"(c[2]), "+f"(c[3])
        : "r"(a[0]), "r"(a[1]), "r"(a[2]), "r"(a[3]), "r"(b[0]), "r"(b[1]));
}

// ---------------- conv stem ----------------
__global__ void conv1_k(const float* __restrict__ x, const float* __restrict__ w,
                        const float* __restrict__ bias,
                        const float* __restrict__ bg, const float* __restrict__ bb,
                        const float* __restrict__ bm, const float* __restrict__ bv)
{
    int idx = blockIdx.x*256 + threadIdx.x;
    if (idx >= B_*C4*L1C) return;
    int l = idx % L1C;
    int c = (idx / L1C) % C4;
    int b = idx / (L1C*C4);
    float acc = bias[c];
    const float* xb = x + (size_t)b*LRAW;
    int p0 = l*5 - 3;
#pragma unroll
    for (int k = 0; k < 10; k++) {
        int p = p0 + k;
        if (p >= 0 && p < LRAW) acc += xb[p] * w[c*10 + k];
    }
    float s = bg[c] * rsqrtf(bv[c] + 1e-5f);
    float t = (acc - bm[c]) * s + bb[c];
    g_s1[idx] = t / (1.f + __expf(-t));
}

__global__ void bnprep_k(const float* __restrict__ cb,
                         const float* __restrict__ bg, const float* __restrict__ bb,
                         const float* __restrict__ bm, const float* __restrict__ bv)
{
    int c = threadIdx.x;
    float s = bg[c] * rsqrtf(bv[c] + 1e-5f);
    g_bnp[c]      = s;
    g_bnp[D_ + c] = (cb[c] - bm[c]) * s + bb[c];
}

__global__ void im2col_k()
{
    int idx = blockIdx.x*256 + threadIdx.x;
    if (idx >= ROWS*C4*3) return;
    int j = idx % (C4*3);
    int m = idx / (C4*3);
    int b = m / LL, l = m % LL;
    int ci = j / 3, kk = j % 3;
    int p = 2*l - 1 + kk;
    g_col[idx] = (p >= 0 && p < L1C) ? g_s1[(b*C4 + ci)*L1C + p] : 0.f;
}

// ---------------- LayerNorm over D=512, one warp per row ----------------
__global__ void ln_k(const float* __restrict__ x, const float* __restrict__ g,
                     const float* __restrict__ bt, float* __restrict__ o)
{
    int row  = (blockIdx.x*blockDim.x + threadIdx.x) >> 5;
    int lane = threadIdx.x & 31;
    const float* xp = x + (size_t)row*D_;
    float v[16];
    float s = 0.f;
#pragma unroll
    for (int i = 0; i < 16; i++) { v[i] = xp[lane + 32*i]; s += v[i]; }
#pragma unroll
    for (int m = 16; m; m >>= 1) s += __shfl_xor_sync(0xffffffffu, s, m);
    float mu = s * (1.f/512.f);
    float vs = 0.f;
#pragma unroll
    for (int i = 0; i < 16; i++) { float d = v[i]-mu; vs += d*d; }
#pragma unroll
    for (int m = 16; m; m >>= 1) vs += __shfl_xor_sync(0xffffffffu, vs, m);
    float inv = rsqrtf(vs * (1.f/512.f) + 1e-5f);
    float* op = o + (size_t)row*D_;
#pragma unroll
    for (int i = 0; i < 16; i++) {
        int c = lane + 32*i;
        op[c] = (v[i]-mu)*inv*g[c] + bt[c];
    }
}

// ---------------- tf32 tensor-core NT GEMM ----------------
// C[M,N] = A[M,K](lda) * B[N,K](ldb)^T
// modes: 0 store, 1 scale/shift, 2 bias+softplus, 3 bias+gelu, 4 residual, 5 bias+residual
template<int BM, int BN, int WM, int WN>
__global__ void __launch_bounds__(256)
gemm_tc(int M, int N, int K, int lda, int ldb,
        const float* __restrict__ A, const float* __restrict__ B,
        float* __restrict__ C, int mode, const float* __restrict__ e1)
{
    constexpr int BK = 16, BKP = 20;
    constexpr int WARPS_M = BM/WM;
    constexpr int MT = WM/16, NT = WN/8;
    __shared__ float As[2][BM][BKP];
    __shared__ float Bs[2][BN][BKP];

    const int tid  = threadIdx.x;
    const int lane = tid & 31, wid = tid >> 5;
    const int wm = wid % WARPS_M, wn = wid / WARPS_M;
    const int bn = blockIdx.x, bm = blockIdx.y;

    const float* Ab = A + (size_t)bm*BM*lda;
    const float* Bb = B + (size_t)bn*BN*ldb;

    float c[MT][NT][4];
#pragma unroll
    for (int i = 0; i < MT; i++)
#pragma unroll
        for (int j = 0; j < NT; j++) {
            c[i][j][0] = 0.f; c[i][j][1] = 0.f; c[i][j][2] = 0.f; c[i][j][3] = 0.f;
        }

    // per-lane ldmatrix row/col within warp tile
    const int a_r = wm*WM + ((lane>>3)&1)*8 + (lane&7);
    const int a_c = (lane>>4)*4;
    const int b_r = wn*WN + (lane>>4)*8 + (lane&7);
    const int b_c = ((lane>>3)&1)*4;

    const uint32_t sA = (uint32_t)__cvta_generic_to_shared(&As[0][0][0]);
    const uint32_t sB = (uint32_t)__cvta_generic_to_shared(&Bs[0][0][0]);

    auto load_tile = [&](int s, int k0) {
        constexpr int AV = BM*BK/4;
#pragma unroll
        for (int v = tid; v < AV; v += 256) {
            int r = v / (BK/4), cc = v % (BK/4);
            cpa16(sA + (uint32_t)(((s*BM + r)*BKP + cc*4)*4),
                  Ab + (size_t)r*lda + k0 + cc*4);
        }
        constexpr int BV = BN*BK/4;
#pragma unroll
        for (int v = tid; v < BV; v += 256) {
            int r = v / (BK/4), cc = v % (BK/4);
            cpa16(sB + (uint32_t)(((s*BN + r)*BKP + cc*4)*4),
                  Bb + (size_t)r*ldb + k0 + cc*4);
        }
    };

    const int iters = K / BK;
    load_tile(0, 0);
    asm volatile("cp.async.commit_group;");

    for (int t = 0; t < iters; t++) {
        if (t + 1 < iters) {
            load_tile((t+1)&1, (t+1)*BK);
            asm volatile("cp.async.commit_group;");
            asm volatile("cp.async.wait_group 1;");
        } else {
            asm volatile("cp.async.wait_group 0;");
        }
        __syncthreads();

        const int s = t & 1;
#pragma unroll
        for (int kk = 0; kk < BK; kk += 8) {
            uint32_t a[MT][4], b[NT][2];
#pragma unroll
            for (int mt = 0; mt < MT; mt++) {
                uint32_t ad = sA + (uint32_t)((((s*BM) + a_r + mt*16)*BKP + kk + a_c)*4);
                ldsm4(a[mt][0], a[mt][1], a[mt][2], a[mt][3], ad);
            }
#pragma unroll
            for (int nt2 = 0; nt2 < NT; nt2 += 2) {
                uint32_t bd = sB + (uint32_t)((((s*BN) + b_r + nt2*8)*BKP + kk + b_c)*4);
                ldsm4(b[nt2][0], b[nt2][1], b[nt2+1][0], b[nt2+1][1], bd);
            }
#pragma unroll
            for (int mt = 0; mt < MT; mt++)
#pragma unroll
                for (int nt = 0; nt < NT; nt++)
                    mma_tf32(c[mt][nt], a[mt], b[nt]);
        }
        __syncthreads();
    }

    // ---------------- epilogue ----------------
    const int qr = lane >> 2;          // quad row 0..7
    const int qc = (lane & 3) * 2;     // col pair
#pragma unroll
    for (int mt = 0; mt < MT; mt++) {
#pragma unroll
        for (int half = 0; half < 2; half++) {
            int row = bm*BM + wm*WM + mt*16 + qr + half*8;
#pragma unroll
            for (int nt = 0; nt < NT; nt++) {
                int col = bn*BN + wn*WN + nt*8 + qc;
                float v0 = c[mt][nt][half*2 + 0];
                float v1 = c[mt][nt][half*2 + 1];
                float* Cp = C + (size_t)row*N + col;
                if (mode == 1) {
                    v0 = v0*e1[col]   + e1[N + col];
                    v1 = v1*e1[col+1] + e1[N + col+1];
                } else if (mode == 2) {
                    float t0 = v0 + e1[col],   t1 = v1 + e1[col+1];
                    v0 = fmaxf(t0, 0.f) + log1pf(__expf(-fabsf(t0)));
                    v1 = fmaxf(t1, 0.f) + log1pf(__expf(-fabsf(t1)));
                } else if (mode == 3) {
                    float t0 = v0 + e1[col],   t1 = v1 + e1[col+1];
                    v0 = 0.5f*t0*(1.f + erff(t0*0.70710678118f));
                    v1 = 0.5f*t1*(1.f + erff(t1*0.70710678118f));
                } else if (mode == 4) {
                    v0 += Cp[0]; v1 += Cp[1];
                } else if (mode == 5) {
                    v0 += Cp[0] + e1[col];
                    v1 += Cp[1] + e1[col+1];
                }
                Cp[0] = v0; Cp[1] = v1;
            }
        }
    }
}

// ---------------- causal depthwise conv (k=4) + SiLU ----------------
__global__ void dwconv_k(const float* __restrict__ cw, const float* __restrict__ cb)
{
    int idx = blockIdx.x*256 + threadIdx.x;
    if (idx >= ROWS*DI) return;
    int d = idx & (DI-1);
    int row = idx >> 10;
    int l = row % LL;
    float s = cb[d];
    const float* base = g_xz + (size_t)(row-3)*2*DI + d;
#pragma unroll
    for (int k = 0; k < 4; k++) {
        int lk = l - 3 + k;
        if (lk >= 0) s += base[k*2*DI] * cw[d*4 + k];
    }
    g_xc[idx] = s / (1.f + __expf(-s));
}

// ---------------- selective scan: 16 lanes per (b,d) channel ----------------
__global__ void scan_k(const float* __restrict__ A_log, const float* __restrict__ Dp)
{
    int gid  = blockIdx.x*128 + threadIdx.x;
    int ch   = gid >> 4;
    int n    = gid & 15;
    int b    = ch >> 10;
    int d    = ch & (DI-1);

    float A   = -__expf(A_log[d*NS + n]);
    float Dpv = Dp[d];
    float h   = 0.f;

    const float* dtp = g_dt  + (size_t)(b*LL)*DI + d;
    const float* xcp = g_xc  + (size_t)(b*LL)*DI + d;
    const float* zp  = g_xz  + (size_t)(b*LL)*2*DI + DI + d;
    const float* bcp = g_dbl + (size_t)(b*LL)*64 + 32 + n;
    float*       yp  = g_y   + (size_t)(b*LL)*DI + d;

    for (int t = 0; t < LL; t++) {
        float dtv = dtp[(size_t)t*DI];
        float xv  = xcp[(size_t)t*DI];
        float Bn  = bcp[(size_t)t*64];
        float Cn  = bcp[(size_t)t*64 + 16];
        float w   = __expf(dtv * A);
        h = h*w + dtv*xv*Bn;
        float part = h * Cn;
        part += __shfl_xor_sync(0xffffffffu, part, 8);
        part += __shfl_xor_sync(0xffffffffu, part, 4);
        part += __shfl_xor_sync(0xffffffffu, part, 2);
        part += __shfl_xor_sync(0xffffffffu, part, 1);
        if (n == 0) {
            float zv  = zp[(size_t)t*2*DI];
            float sil = zv / (1.f + __expf(-zv));
            yp[(size_t)t*DI] = (part + xv*Dpv) * sil;
        }
    }
}

// ---------------- mean over L ----------------
__global__ void mean_part_k()
{
    int d = threadIdx.x;
    int b = blockIdx.x & 3;
    int chunk = blockIdx.x >> 2;
    float s = 0.f;
    const float* up = g_u + (size_t)(b*LL + chunk*100)*D_ + d;
    for (int l = 0; l < 100; l++) s += up[(size_t)l*D_];
    g_part[blockIdx.x*D_ + d] = s;
}
__global__ void mean_fin_k(float* __restrict__ out)
{
    int i = blockIdx.x*256 + threadIdx.x;
    int b = i >> 9, d = i & 511;
    float s = 0.f;
#pragma unroll
    for (int c = 0; c < 8; c++) s += g_part[(c*4 + b)*D_ + d];
    out[i] = s * (1.f/800.f);
}

// ---------------- driver ----------------
extern "C" void kernel_launch(void* const* d_in, const int* in_sizes, int n_in,
                              void* d_out, int out_size)
{
    const float* x    = (const float*)d_in[0];
    const float* c1w  = (const float*)d_in[1];
    const float* c1b  = (const float*)d_in[2];
    const float* b1g  = (const float*)d_in[3];
    const float* b1b  = (const float*)d_in[4];
    const float* b1m  = (const float*)d_in[5];
    const float* b1v  = (const float*)d_in[6];
    const float* c2w  = (const float*)d_in[7];
    const float* c2b  = (const float*)d_in[8];
    const float* b2g  = (const float*)d_in[9];
    const float* b2b  = (const float*)d_in[10];
    const float* b2m  = (const float*)d_in[11];
    const float* b2v  = (const float*)d_in[12];
    const float* ln1g = (const float*)d_in[13];
    const float* ln1b = (const float*)d_in[14];
    const float* inw  = (const float*)d_in[15];
    const float* cw   = (const float*)d_in[16];
    const float* cb   = (const float*)d_in[17];
    const float* xpw  = (const float*)d_in[18];
    const float* dtw  = (const float*)d_in[19];
    const float* dtb  = (const float*)d_in[20];
    const float* alog = (const float*)d_in[21];
    const float* dp   = (const float*)d_in[22];
    const float* outw = (const float*)d_in[23];
    const float* ln2g = (const float*)d_in[24];
    const float* ln2b = (const float*)d_in[25];
    const float* m1w  = (const float*)d_in[26];
    const float* m1b  = (const float*)d_in[27];
    const float* m2w  = (const float*)d_in[28];
    const float* m2b  = (const float*)d_in[29];
    const float* fng  = (const float*)d_in[30];
    const float* fnb  = (const float*)d_in[31];

    float *h, *u, *xz, *xc, *dbl, *dt, *y, *col, *bnp;
    cudaGetSymbolAddress((void**)&h,   g_h);
    cudaGetSymbolAddress((void**)&u,   g_u);
    cudaGetSymbolAddress((void**)&xz,  g_xz);
    cudaGetSymbolAddress((void**)&xc,  g_xc);
    cudaGetSymbolAddress((void**)&dbl, g_dbl);
    cudaGetSymbolAddress((void**)&dt,  g_dt);
    cudaGetSymbolAddress((void**)&y,   g_y);
    cudaGetSymbolAddress((void**)&col, g_col);
    cudaGetSymbolAddress((void**)&bnp, g_bnp);

    // ---- stem ----
    conv1_k<<<(B_*C4*L1C + 255)/256, 256>>>(x, c1w, c1b, b1g, b1b, b1m, b1v);
    bnprep_k<<<1, 512>>>(c2b, b2g, b2b, b2m, b2v);
    im2col_k<<<(ROWS*C4*3 + 255)/256, 256>>>();
    gemm_tc<128,128,64,32><<<dim3(D_/128, ROWS/128), 256>>>(
        ROWS, D_, C4*3, C4*3, C4*3, col, c2w, h, 1, bnp);

    // ---- layers ----
    for (int i = 0; i < NLAY; i++) {
        ln_k<<<ROWS/8, 256>>>(h, ln1g + i*D_, ln1b + i*D_, u);
        gemm_tc<128,128,64,32><<<dim3(2*DI/128, ROWS/128), 256>>>(
            ROWS, 2*DI, D_, D_, D_, u, inw + (size_t)i*2*DI*D_, xz, 0, nullptr);
        dwconv_k<<<(ROWS*DI + 255)/256, 256>>>(cw + (size_t)i*DI*4, cb + i*DI);
        gemm_tc<128,64,32,32><<<dim3(1, ROWS/128), 256>>>(
            ROWS, 64, DI, DI, DI, xc, xpw + (size_t)i*64*DI, dbl, 0, nullptr);
        gemm_tc<128,128,64,32><<<dim3(DI/128, ROWS/128), 256>>>(
            ROWS, DI, RK, 64, RK, dbl, dtw + (size_t)i*DI*RK, dt, 2, dtb + i*DI);
        scan_k<<<512, 128>>>(alog + (size_t)i*DI*NS, dp + i*DI);
        gemm_tc<128,128,64,32><<<dim3(D_/128, ROWS/128), 256>>>(
            ROWS, D_, DI, DI, DI, y, outw + (size_t)i*D_*DI, h, 4, nullptr);

        ln_k<<<ROWS/8, 256>>>(h, ln2g + i*D_, ln2b + i*D_, u);
        gemm_tc<128,128,64,32><<<dim3(DI/128, ROWS/128), 256>>>(
            ROWS, DI, D_, D_, D_, u, m1w + (size_t)i*DI*D_, xc, 3, m1b + i*DI);
        gemm_tc<128,128,64,32><<<dim3(D_/128, ROWS/128), 256>>>(
            ROWS, D_, DI, DI, DI, xc, m2w + (size_t)i*D_*DI, h, 5, m2b + i*D_);
    }

    // ---- final LN + mean ----
    ln_k<<<ROWS/8, 256>>>(h, fng, fnb, u);
    mean_part_k<<<32, 512>>>();
    mean_fin_k<<<8, 256>>>((float*)d_out);
}

// round 3
// speedup vs baseline: 1.8988x; 1.2485x over previous
#include <cuda_runtime.h>
#include <math.h>
#include <stdint.h>

// ---------------- problem constants ----------------
#define B_    4
#define LRAW  8000
#define D_    512
#define NLAY  4
#define NS    16
#define DI    1024
#define RK    32
#define L1C   1600
#define LL    800
#define C4    128
#define ROWS  (B_*LL)          // 3200

// ---------------- scratch (device globals; no allocation) ----------------
__device__ float g_h  [ROWS*D_];
__device__ float g_u  [ROWS*D_];
__device__ float g_xz [ROWS*2*DI];
__device__ float g_xc [ROWS*DI];
__device__ float g_dbl[ROWS*64];
__device__ float g_dblp[4*ROWS*64];
__device__ float g_dt [ROWS*DI];
__device__ float g_y  [ROWS*DI];
__device__ float g_s1 [B_*C4*L1C];
__device__ float g_col[ROWS*C4*3];
__device__ float g_bnp[2*D_];
__device__ float g_part[32*D_];

// ---------------- PTX helpers ----------------
__device__ __forceinline__ void cpa16(uint32_t s, const void* g) {
    asm volatile("cp.async.ca.shared.global [%0], [%1], 16;" :: "r"(s), "l"(g));
}
__device__ __forceinline__ void ldsm4(uint32_t& r0, uint32_t& r1, uint32_t& r2, uint32_t& r3,
                                      uint32_t addr) {
    asm volatile("ldmatrix.sync.aligned.m8n8.x4.shared.b16 {%0,%1,%2,%3}, [%4];"
        : "=r"(r0), "=r"(r1), "=r"(r2), "=r"(r3) : "r"(addr));
}
__device__ __forceinline__ void mma_tf32(float* c, const uint32_t* a, const uint32_t* b) {
    asm volatile("mma.sync.aligned.m16n8k8.row.col.f32.tf32.tf32.f32 "
        "{%0,%1,%2,%3},{%4,%5,%6,%7},{%8,%9},{%0,%1,%2,%3};"
        : "+f"(c[0]), "+f"(c[1]), "+f"(c[2]), "+f"(c[3])
        : "r"(a[0]), "r"(a[1]), "r"(a[2]), "r"(a[3]), "r"(b[0]), "r"(b[1]));
}
// split fp32 into tf32 hi + tf32 lo (3-term tf32 => ~fp32 product precision)
__device__ __forceinline__ void tsplit(uint32_t raw, uint32_t& hi, uint32_t& lo) {
    float f = __uint_as_float(raw);
    asm("cvt.rna.tf32.f32 %0, %1;" : "=r"(hi) : "f"(f));
    float s = f - __uint_as_float(hi);
    asm("cvt.rna.tf32.f32 %0, %1;" : "=r"(lo) : "f"(s));
}

// ---------------- conv stem ----------------
__global__ void conv1_k(const float* __restrict__ x, const float* __restrict__ w,
                        const float* __restrict__ bias,
                        const float* __restrict__ bg, const float* __restrict__ bb,
                        const float* __restrict__ bm, const float* __restrict__ bv)
{
    int idx = blockIdx.x*256 + threadIdx.x;
    if (idx >= B_*C4*L1C) return;
    int l = idx % L1C;
    int c = (idx / L1C) % C4;
    int b = idx / (L1C*C4);
    float acc = bias[c];
    const float* xb = x + (size_t)b*LRAW;
    int p0 = l*5 - 3;
#pragma unroll
    for (int k = 0; k < 10; k++) {
        int p = p0 + k;
        if (p >= 0 && p < LRAW) acc += xb[p] * w[c*10 + k];
    }
    float s = bg[c] * rsqrtf(bv[c] + 1e-5f);
    float t = (acc - bm[c]) * s + bb[c];
    g_s1[idx] = t / (1.f + __expf(-t));
}

__global__ void bnprep_k(const float* __restrict__ cb,
                         const float* __restrict__ bg, const float* __restrict__ bb,
                         const float* __restrict__ bm, const float* __restrict__ bv)
{
    int c = threadIdx.x;
    float s = bg[c] * rsqrtf(bv[c] + 1e-5f);
    g_bnp[c]      = s;
    g_bnp[D_ + c] = (cb[c] - bm[c]) * s + bb[c];
}

__global__ void im2col_k()
{
    int idx = blockIdx.x*256 + threadIdx.x;
    if (idx >= ROWS*C4*3) return;
    int j = idx % (C4*3);
    int m = idx / (C4*3);
    int b = m / LL, l = m % LL;
    int ci = j / 3, kk = j % 3;
    int p = 2*l - 1 + kk;
    g_col[idx] = (p >= 0 && p < L1C) ? g_s1[(b*C4 + ci)*L1C + p] : 0.f;
}

// ---------------- LayerNorm over D=512, one warp per row ----------------
__global__ void ln_k(const float* __restrict__ x, const float* __restrict__ g,
                     const float* __restrict__ bt, float* __restrict__ o)
{
    int row  = (blockIdx.x*blockDim.x + threadIdx.x) >> 5;
    int lane = threadIdx.x & 31;
    const float* xp = x + (size_t)row*D_;
    float v[16];
    float s = 0.f;
#pragma unroll
    for (int i = 0; i < 16; i++) { v[i] = xp[lane + 32*i]; s += v[i]; }
#pragma unroll
    for (int m = 16; m; m >>= 1) s += __shfl_xor_sync(0xffffffffu, s, m);
    float mu = s * (1.f/512.f);
    float vs = 0.f;
#pragma unroll
    for (int i = 0; i < 16; i++) { float d = v[i]-mu; vs += d*d; }
#pragma unroll
    for (int m = 16; m; m >>= 1) vs += __shfl_xor_sync(0xffffffffu, vs, m);
    float inv = rsqrtf(vs * (1.f/512.f) + 1e-5f);
    float* op = o + (size_t)row*D_;
#pragma unroll
    for (int i = 0; i < 16; i++) {
        int c = lane + 32*i;
        op[c] = (v[i]-mu)*inv*g[c] + bt[c];
    }
}

// ---------------- 3xTF32 tensor-core NT GEMM ----------------
// C[M,N] = A[M,K](lda) * B[N,K](ldb)^T, BM=128, BN=64, 8 warps (WM=32,WN=32)
// If gridDim.z > 1: split-K — slice z handles K elems at offset z*K, C -> C + z*M*N.
// modes: 0 store, 1 scale/shift, 2 bias+softplus, 3 bias+gelu, 4 residual, 5 bias+residual
__global__ void __launch_bounds__(256, 2)
gemm_tc(int M, int N, int K, int lda, int ldb,
        const float* __restrict__ A, const float* __restrict__ B,
        float* __restrict__ C, int mode, const float* __restrict__ e1)
{
    constexpr int BM = 128, BN = 64, BK = 16, BKP = 20;
    constexpr int MT = 2, NT = 4;
    __shared__ float As[3][BM][BKP];
    __shared__ float Bs[3][BN][BKP];

    const int tid  = threadIdx.x;
    const int lane = tid & 31, wid = tid >> 5;
    const int wm = wid & 3, wn = wid >> 2;          // 4 x 2 warps
    const int bn = blockIdx.x, bm = blockIdx.y, bz = blockIdx.z;

    const float* Ab = A + (size_t)bm*BM*lda + (size_t)bz*K;
    const float* Bb = B + (size_t)bn*BN*ldb + (size_t)bz*K;
    if (gridDim.z > 1) C += (size_t)bz*M*N;

    float c[MT][NT][4];
#pragma unroll
    for (int i = 0; i < MT; i++)
#pragma unroll
        for (int j = 0; j < NT; j++) {
            c[i][j][0]=0.f; c[i][j][1]=0.f; c[i][j][2]=0.f; c[i][j][3]=0.f;
        }

    const int a_r = wm*32 + ((lane>>3)&1)*8 + (lane&7);
    const int a_c = (lane>>4)*4;
    const int b_r = wn*32 + (lane>>4)*8 + (lane&7);
    const int b_c = ((lane>>3)&1)*4;

    const uint32_t sA = (uint32_t)__cvta_generic_to_shared(&As[0][0][0]);
    const uint32_t sB = (uint32_t)__cvta_generic_to_shared(&Bs[0][0][0]);

    auto load_tile = [&](int s, int k0) {
#pragma unroll
        for (int v = tid; v < BM*BK/4; v += 256) {           // 512 float4
            int r = v >> 2, cc = (v & 3) * 4;
            cpa16(sA + (uint32_t)(((s*BM + r)*BKP + cc)*4),
                  Ab + (size_t)r*lda + k0 + cc);
        }
        {
            int v = tid;                                     // 256 float4
            int r = v >> 2, cc = (v & 3) * 4;
            cpa16(sB + (uint32_t)(((s*BN + r)*BKP + cc)*4),
                  Bb + (size_t)r*ldb + k0 + cc);
        }
    };

    const int iters = K / BK;
    load_tile(0, 0);
    asm volatile("cp.async.commit_group;");
    if (iters > 1) load_tile(1, BK);
    asm volatile("cp.async.commit_group;");

    for (int t = 0; t < iters; t++) {
        if (t + 2 < iters) {
            load_tile((t+2)%3, (t+2)*BK);
            asm volatile("cp.async.commit_group;");
            asm volatile("cp.async.wait_group 2;");
        } else if (t + 1 < iters) {
            asm volatile("cp.async.wait_group 1;");
        } else {
            asm volatile("cp.async.wait_group 0;");
        }
        __syncthreads();

        const int s = t % 3;
#pragma unroll
        for (int kk = 0; kk < BK; kk += 8) {
            uint32_t a[MT][4], ah[MT][4], al[MT][4];
            uint32_t b[NT][2], bh[NT][2], bl[NT][2];
#pragma unroll
            for (int mt = 0; mt < MT; mt++) {
                uint32_t ad = sA + (uint32_t)((((s*BM) + a_r + mt*16)*BKP + kk + a_c)*4);
                ldsm4(a[mt][0], a[mt][1], a[mt][2], a[mt][3], ad);
            }
#pragma unroll
            for (int nt2 = 0; nt2 < NT; nt2 += 2) {
                uint32_t bd = sB + (uint32_t)((((s*BN) + b_r + nt2*8)*BKP + kk + b_c)*4);
                ldsm4(b[nt2][0], b[nt2][1], b[nt2+1][0], b[nt2+1][1], bd);
            }
#pragma unroll
            for (int mt = 0; mt < MT; mt++)
#pragma unroll
                for (int q = 0; q < 4; q++) tsplit(a[mt][q], ah[mt][q], al[mt][q]);
#pragma unroll
            for (int nt = 0; nt < NT; nt++)
#pragma unroll
                for (int q = 0; q < 2; q++) tsplit(b[nt][q], bh[nt][q], bl[nt][q]);
#pragma unroll
            for (int mt = 0; mt < MT; mt++)
#pragma unroll
                for (int nt = 0; nt < NT; nt++) {
                    mma_tf32(c[mt][nt], al[mt], bh[nt]);
                    mma_tf32(c[mt][nt], ah[mt], bl[nt]);
                    mma_tf32(c[mt][nt], ah[mt], bh[nt]);
                }
        }
        __syncthreads();
    }

    // ---------------- epilogue ----------------
    const int qr = lane >> 2;
    const int qc = (lane & 3) * 2;
#pragma unroll
    for (int mt = 0; mt < MT; mt++) {
#pragma unroll
        for (int half = 0; half < 2; half++) {
            int row = bm*BM + wm*32 + mt*16 + qr + half*8;
#pragma unroll
            for (int nt = 0; nt < NT; nt++) {
                int col = bn*BN + wn*32 + nt*8 + qc;
                float v0 = c[mt][nt][half*2 + 0];
                float v1 = c[mt][nt][half*2 + 1];
                float* Cp = C + (size_t)row*N + col;
                if (mode == 1) {
                    v0 = v0*e1[col]   + e1[N + col];
                    v1 = v1*e1[col+1] + e1[N + col+1];
                } else if (mode == 2) {
                    float t0 = v0 + e1[col],   t1 = v1 + e1[col+1];
                    v0 = fmaxf(t0, 0.f) + log1pf(__expf(-fabsf(t0)));
                    v1 = fmaxf(t1, 0.f) + log1pf(__expf(-fabsf(t1)));
                } else if (mode == 3) {
                    float t0 = v0 + e1[col],   t1 = v1 + e1[col+1];
                    v0 = 0.5f*t0*(1.f + erff(t0*0.70710678118f));
                    v1 = 0.5f*t1*(1.f + erff(t1*0.70710678118f));
                } else if (mode == 4) {
                    v0 += Cp[0]; v1 += Cp[1];
                } else if (mode == 5) {
                    v0 += Cp[0] + e1[col];
                    v1 += Cp[1] + e1[col+1];
                }
                Cp[0] = v0; Cp[1] = v1;
            }
        }
    }
}

// ---------------- split-K combine for xp GEMM ----------------
__global__ void dblsum_k()
{
    int i = blockIdx.x*256 + threadIdx.x;
    if (i < ROWS*64)
        g_dbl[i] = g_dblp[i] + g_dblp[ROWS*64 + i] + g_dblp[2*ROWS*64 + i] + g_dblp[3*ROWS*64 + i];
}

// ---------------- causal depthwise conv (k=4) + SiLU ----------------
__global__ void dwconv_k(const float* __restrict__ cw, const float* __restrict__ cb)
{
    int idx = blockIdx.x*256 + threadIdx.x;
    if (idx >= ROWS*DI) return;
    int d = idx & (DI-1);
    int row = idx >> 10;
    int l = row % LL;
    float s = cb[d];
    const float* base = g_xz + (size_t)(row-3)*2*DI + d;
#pragma unroll
    for (int k = 0; k < 4; k++) {
        int lk = l - 3 + k;
        if (lk >= 0) s += base[k*2*DI] * cw[d*4 + k];
    }
    g_xc[idx] = s / (1.f + __expf(-s));
}

// ---------------- selective scan: smem-staged, 8 channels x 16 states / block ----
#define SCT 50
__global__ void __launch_bounds__(128)
scan_k(const float* __restrict__ A_log, const float* __restrict__ Dp)
{
    __shared__ float dt_s[SCT][8], xc_s[SCT][8], z_s[SCT][8];
    __shared__ float BC[SCT][32];
    __shared__ float ys[SCT][8];

    const int tid = threadIdx.x;
    const int bid = blockIdx.x;          // 512 blocks
    const int b   = bid >> 7;
    const int d0  = (bid & 127) * 8;
    const int ch  = tid >> 4;            // 0..7
    const int n   = tid & 15;
    const int d   = d0 + ch;

    const float A   = -__expf(A_log[d*NS + n]);
    const float Dpv = Dp[d];
    float h = 0.f;
    const size_t rb = (size_t)b*LL;

    for (int t0 = 0; t0 < LL; t0 += SCT) {
        // ---- stage ----
        if (tid < SCT*2) {
            int tt = tid >> 1, sg = (tid & 1) * 4;
            size_t r = rb + t0 + tt;
            *(float4*)&dt_s[tt][sg] = *(const float4*)&g_dt[r*DI + d0 + sg];
            *(float4*)&xc_s[tt][sg] = *(const float4*)&g_xc[r*DI + d0 + sg];
            *(float4*)&z_s[tt][sg]  = *(const float4*)&g_xz[r*2*DI + DI + d0 + sg];
        }
        for (int j = tid; j < SCT*8; j += 128) {
            int tt = j >> 3, sg = (j & 7) * 4;
            size_t r = rb + t0 + tt;
            *(float4*)&BC[tt][sg] = *(const float4*)&g_dbl[r*64 + 32 + sg];
        }
        __syncthreads();

        // ---- compute ----
#pragma unroll 5
        for (int tt = 0; tt < SCT; tt++) {
            float dtv = dt_s[tt][ch];
            float xv  = xc_s[tt][ch];
            float Bn  = BC[tt][n];
            float Cn  = BC[tt][16 + n];
            float w   = __expf(dtv * A);
            h = h*w + dtv*xv*Bn;
            float part = h * Cn;
            part += __shfl_xor_sync(0xffffffffu, part, 8);
            part += __shfl_xor_sync(0xffffffffu, part, 4);
            part += __shfl_xor_sync(0xffffffffu, part, 2);
            part += __shfl_xor_sync(0xffffffffu, part, 1);
            if (n == 0) {
                float zv  = z_s[tt][ch];
                float sil = zv / (1.f + __expf(-zv));
                ys[tt][ch] = (part + xv*Dpv) * sil;
            }
        }
        __syncthreads();

        // ---- write out ----
        if (tid < SCT*2) {
            int tt = tid >> 1, sg = (tid & 1) * 4;
            *(float4*)&g_y[(rb + t0 + tt)*DI + d0 + sg] = *(float4*)&ys[tt][sg];
        }
    }
}

// ---------------- mean over L ----------------
__global__ void mean_part_k()
{
    int d = threadIdx.x;
    int b = blockIdx.x & 3;
    int chunk = blockIdx.x >> 2;
    float s = 0.f;
    const float* up = g_u + (size_t)(b*LL + chunk*100)*D_ + d;
    for (int l = 0; l < 100; l++) s += up[(size_t)l*D_];
    g_part[blockIdx.x*D_ + d] = s;
}
__global__ void mean_fin_k(float* __restrict__ out)
{
    int i = blockIdx.x*256 + threadIdx.x;
    int b = i >> 9, d = i & 511;
    float s = 0.f;
#pragma unroll
    for (int c = 0; c < 8; c++) s += g_part[(c*4 + b)*D_ + d];
    out[i] = s * (1.f/800.f);
}

// ---------------- driver ----------------
extern "C" void kernel_launch(void* const* d_in, const int* in_sizes, int n_in,
                              void* d_out, int out_size)
{
    const float* x    = (const float*)d_in[0];
    const float* c1w  = (const float*)d_in[1];
    const float* c1b  = (const float*)d_in[2];
    const float* b1g  = (const float*)d_in[3];
    const float* b1b  = (const float*)d_in[4];
    const float* b1m  = (const float*)d_in[5];
    const float* b1v  = (const float*)d_in[6];
    const float* c2w  = (const float*)d_in[7];
    const float* c2b  = (const float*)d_in[8];
    const float* b2g  = (const float*)d_in[9];
    const float* b2b  = (const float*)d_in[10];
    const float* b2m  = (const float*)d_in[11];
    const float* b2v  = (const float*)d_in[12];
    const float* ln1g = (const float*)d_in[13];
    const float* ln1b = (const float*)d_in[14];
    const float* inw  = (const float*)d_in[15];
    const float* cw   = (const float*)d_in[16];
    const float* cb   = (const float*)d_in[17];
    const float* xpw  = (const float*)d_in[18];
    const float* dtw  = (const float*)d_in[19];
    const float* dtb  = (const float*)d_in[20];
    const float* alog = (const float*)d_in[21];
    const float* dp   = (const float*)d_in[22];
    const float* outw = (const float*)d_in[23];
    const float* ln2g = (const float*)d_in[24];
    const float* ln2b = (const float*)d_in[25];
    const float* m1w  = (const float*)d_in[26];
    const float* m1b  = (const float*)d_in[27];
    const float* m2w  = (const float*)d_in[28];
    const float* m2b  = (const float*)d_in[29];
    const float* fng  = (const float*)d_in[30];
    const float* fnb  = (const float*)d_in[31];

    float *h, *u, *xz, *xc, *dbl, *dblp, *dt, *y, *col, *bnp;
    cudaGetSymbolAddress((void**)&h,    g_h);
    cudaGetSymbolAddress((void**)&u,    g_u);
    cudaGetSymbolAddress((void**)&xz,   g_xz);
    cudaGetSymbolAddress((void**)&xc,   g_xc);
    cudaGetSymbolAddress((void**)&dbl,  g_dbl);
    cudaGetSymbolAddress((void**)&dblp, g_dblp);
    cudaGetSymbolAddress((void**)&dt,   g_dt);
    cudaGetSymbolAddress((void**)&y,    g_y);
    cudaGetSymbolAddress((void**)&col,  g_col);
    cudaGetSymbolAddress((void**)&bnp,  g_bnp);

    // ---- stem ----
    conv1_k<<<(B_*C4*L1C + 255)/256, 256>>>(x, c1w, c1b, b1g, b1b, b1m, b1v);
    bnprep_k<<<1, 512>>>(c2b, b2g, b2b, b2m, b2v);
    im2col_k<<<(ROWS*C4*3 + 255)/256, 256>>>();
    gemm_tc<<<dim3(D_/64, ROWS/128), 256>>>(
        ROWS, D_, C4*3, C4*3, C4*3, col, c2w, h, 1, bnp);

    // ---- layers ----
    for (int i = 0; i < NLAY; i++) {
        ln_k<<<ROWS/8, 256>>>(h, ln1g + i*D_, ln1b + i*D_, u);
        gemm_tc<<<dim3(2*DI/64, ROWS/128), 256>>>(
            ROWS, 2*DI, D_, D_, D_, u, inw + (size_t)i*2*DI*D_, xz, 0, nullptr);
        dwconv_k<<<(ROWS*DI + 255)/256, 256>>>(cw + (size_t)i*DI*4, cb + i*DI);
        gemm_tc<<<dim3(1, ROWS/128, 4), 256>>>(                      // split-K x4
            ROWS, 64, DI/4, DI, DI, xc, xpw + (size_t)i*64*DI, dblp, 0, nullptr);
        dblsum_k<<<(ROWS*64 + 255)/256, 256>>>();
        gemm_tc<<<dim3(DI/64, ROWS/128), 256>>>(
            ROWS, DI, RK, 64, RK, dbl, dtw + (size_t)i*DI*RK, dt, 2, dtb + i*DI);
        scan_k<<<512, 128>>>(alog + (size_t)i*DI*NS, dp + i*DI);
        gemm_tc<<<dim3(D_/64, ROWS/128), 256>>>(
            ROWS, D_, DI, DI, DI, y, outw + (size_t)i*D_*DI, h, 4, nullptr);

        ln_k<<<ROWS/8, 256>>>(h, ln2g + i*D_, ln2b + i*D_, u);
        gemm_tc<<<dim3(DI/64, ROWS/128), 256>>>(
            ROWS, DI, D_, D_, D_, u, m1w + (size_t)i*DI*D_, xc, 3, m1b + i*DI);
        gemm_tc<<<dim3(D_/64, ROWS/128), 256>>>(
            ROWS, D_, DI, DI, DI, xc, m2w + (size_t)i*D_*DI, h, 5, m2b + i*D_);
    }

    // ---- final LN + mean ----
    ln_k<<<ROWS/8, 256>>>(h, fng, fnb, u);
    mean_part_k<<<32, 512>>>();
    mean_fin_k<<<8, 256>>>((float*)d_out);
}